// round 4
// baseline (speedup 1.0000x reference)
#include <cuda_runtime.h>
#include <float.h>

#define Bv 64
#define Nv 1024
#define Dv 128
#define Kv 6
#define CHUNKS 8          // 128 rows per main block, grid = 8 x 64 = 512

__device__ float  g_ABC[Kv * Dv * 3];               // [k][d][{A,B,C}]
__device__ float  g_partial[Bv * CHUNKS * 2 * Dv];  // [b][chunk][half][d]
__device__ float4 g_sorted[Bv * Nv];                // (xb, yb, x0[orig], y0[orig])
__device__ int    g_sid[Bv * Nv];                   // orig index, sorted order
__device__ int    g_count;                          // completion counter (self-resets)

// ---------------------------------------------------------------------------
// Setup kernel: blocks 0..63  -> per-batch bitonic x-sort (payload y, idx)
//               blocks 64..111 -> fold W2d/b2d through Wnb (one warp per (k,d))
// ---------------------------------------------------------------------------
__global__ __launch_bounds__(512) void setup_kernel(
    const float* __restrict__ loc,
    const float* __restrict__ W2d, const float* __restrict__ b2d,
    const float* __restrict__ Wnb)
{
    __shared__ float kx[Nv];
    __shared__ float ky[Nv];
    __shared__ int   kid[Nv];
    const int t = threadIdx.x;

    if (blockIdx.x >= Bv) {
        // ---- abc fold: 48 blocks x 16 warps = 768 warps = 6k x 128d ----
        int wid  = (blockIdx.x - Bv) * 16 + (t >> 5);
        int k    = wid >> 7, d = wid & (Dv - 1);
        int lane = t & 31;
        const float4* w4 = (const float4*)(Wnb + (size_t)d * (Kv * Dv) + k * Dv);
        float4 v  = w4[lane];
        const float4* w2 = (const float4*)W2d;
        float4 p0 = w2[lane * 2], p1 = w2[lane * 2 + 1];
        float4 bb = ((const float4*)b2d)[lane];
        float A = fmaf(v.x, p0.x, fmaf(v.y, p0.z, fmaf(v.z, p1.x, v.w * p1.z)));
        float B = fmaf(v.x, p0.y, fmaf(v.y, p0.w, fmaf(v.z, p1.y, v.w * p1.w)));
        float C = fmaf(v.x, bb.x, fmaf(v.y, bb.y, fmaf(v.z, bb.z, v.w * bb.w)));
#pragma unroll
        for (int s = 16; s > 0; s >>= 1) {
            A += __shfl_xor_sync(0xffffffffu, A, s);
            B += __shfl_xor_sync(0xffffffffu, B, s);
            C += __shfl_xor_sync(0xffffffffu, C, s);
        }
        if (lane == 0) {
            int base = (k * Dv + d) * 3;
            g_ABC[base + 0] = A; g_ABC[base + 1] = B; g_ABC[base + 2] = C;
        }
        return;
    }

    // ---- per-batch bitonic sort by x ----
    const int b = blockIdx.x;
    const float2* lb = (const float2*)(loc + (size_t)b * Nv * 2);
    for (int i = t; i < Nv; i += 512) {
        float2 p = lb[i];
        kx[i] = p.x; ky[i] = p.y; kid[i] = i;
    }
    __syncthreads();
    for (int k = 2; k <= Nv; k <<= 1) {
        for (int j = k >> 1; j > 0; j >>= 1) {
            for (int i = t; i < Nv; i += 512) {
                int ixj = i ^ j;
                if (ixj > i) {
                    bool up = ((i & k) == 0);
                    float xa = kx[i], xb = kx[ixj];
                    if (up ? (xa > xb) : (xa < xb)) {
                        kx[i] = xb; kx[ixj] = xa;
                        float ya = ky[i]; ky[i] = ky[ixj]; ky[ixj] = ya;
                        int ia = kid[i]; kid[i] = kid[ixj]; kid[ixj] = ia;
                    }
                }
            }
            __syncthreads();
        }
    }
    const float2* l0 = (const float2*)loc;   // batch-0 coords
    for (int i = t; i < Nv; i += 512) {
        int gid = kid[i];
        float2 p0 = l0[gid];
        g_sorted[(size_t)b * Nv + i] = make_float4(kx[i], ky[i], p0.x, p0.y);
        g_sid[(size_t)b * Nv + i]    = gid;
    }
}

// ---------------------------------------------------------------------------
// Main kernel: 256 threads, 128 rows/block. Thread = (row, direction).
//   phase 2: directional outward window scan (unroll x4, deferred prune),
//            branchless sorted top-6 insert; halves merged two-pointer.
//   phase 3: fused affine features + leaky_relu; last block runs tail.
// ---------------------------------------------------------------------------
__global__ __launch_bounds__(256) void main_kernel(
    const float* __restrict__ deadline,
    const float* __restrict__ W3d, const float* __restrict__ b3d,
    const float* __restrict__ bnb,
    const float* __restrict__ depot, const float* __restrict__ Wdep,
    const float* __restrict__ bdep, float* __restrict__ h_out)
{
    __shared__ float2 sxyv[Nv];        // sorted batch-b coords       8 KB
    __shared__ float2 s0s[Nv];         // batch-0 coords, sorted ord  8 KB
    __shared__ int    sid[Nv];         // orig idx, sorted order      4 KB
    __shared__ float4 srow[128];       // (x, y, deadline, origbits)  2 KB
    __shared__ float2 snb[128 * Kv];   // neighbor batch-0 coords     6 KB
    __shared__ float4 sW3[Dv];         // (w0,w1,w2, base)            2 KB
    __shared__ float2 sAB[Kv * Dv];    // (A_k[d], B_k[d])            6 KB
    __shared__ float  pdm[128 * Kv];   // right-scanner top-6 dists   3 KB
    __shared__ int    pim[128 * Kv];   // right-scanner top-6 pos     3 KB
    __shared__ int    sLast;

    const int b = blockIdx.y, chunk = blockIdx.x, t = threadIdx.x;

    {
        const float4* gs = g_sorted + (size_t)b * Nv;
        const int*    gi = g_sid    + (size_t)b * Nv;
        for (int i = t; i < Nv; i += 256) {
            float4 q = gs[i];
            sxyv[i] = make_float2(q.x, q.y);
            s0s[i]  = make_float2(q.z, q.w);
            sid[i]  = gi[i];
        }
    }
    if (t < Dv) {
        float sumC = 0.f;
#pragma unroll
        for (int k = 0; k < Kv; k++) {
            int base = (k * Dv + t) * 3;
            sAB[k * Dv + t] = make_float2(g_ABC[base], g_ABC[base + 1]);
            sumC += g_ABC[base + 2];
        }
        sW3[t] = make_float4(W3d[t * 3 + 0], W3d[t * 3 + 1], W3d[t * 3 + 2],
                             b3d[t] + bnb[t] + sumC);
    }
    __syncthreads();

    // ---- phase 2: directional scan ----
    const int rloc = t & 127;
    const int dir  = t >> 7;              // 0 = left (incl. self), 1 = right
    const int p    = chunk * 128 + rloc;
    const float2 m = sxyv[p];
    const float mx = m.x, my = m.y;

    float d0, d1 = FLT_MAX, d2 = FLT_MAX, d3 = FLT_MAX, d4 = FLT_MAX, d5 = FLT_MAX;
    int   i0, i1 = 0, i2 = 0, i3 = 0, i4 = 0, i5 = 0;
    d0 = dir ? FLT_MAX : 0.f;             // self: dd = 0
    i0 = dir ? 0 : p;

#define INS(dd, cj)  do {                                                    \
        bool c0 = dd < d0, c1 = dd < d1, c2 = dd < d2,                       \
             c3 = dd < d3, c4 = dd < d4, c5 = dd < d5;                       \
        float m0 = fmaxf(d0, dd), m1 = fmaxf(d1, dd), m2 = fmaxf(d2, dd),    \
              m3 = fmaxf(d3, dd), m4 = fmaxf(d4, dd);                        \
        int   w0 = c0 ? i0 : cj, w1 = c1 ? i1 : cj, w2 = c2 ? i2 : cj,       \
              w3 = c3 ? i3 : cj, w4 = c4 ? i4 : cj;                          \
        d5 = c5 ? m4 : d5;  i5 = c5 ? w4 : i5;                               \
        d4 = c4 ? m3 : d4;  i4 = c4 ? w3 : i4;                               \
        d3 = c3 ? m2 : d3;  i3 = c3 ? w2 : i3;                               \
        d2 = c2 ? m1 : d2;  i2 = c2 ? w1 : i2;                               \
        d1 = c1 ? m0 : d1;  i1 = c1 ? w0 : i1;                               \
        d0 = c0 ? dd : d0;  i0 = c0 ? cj : i0;                               \
    } while (0)

#define CAND(cv, cj, DXX) {                                                  \
        float dx  = __fadd_rn(cv.x, -mx);                                    \
        float dy  = __fadd_rn(cv.y, -my);                                    \
        DXX = __fmul_rn(dx, dx);                                             \
        float dd  = __fadd_rn(DXX, __fmul_rn(dy, dy));                       \
        INS(dd, cj);                                                         \
    }

    if (dir == 0) {                        // leftward
        int j = p - 1; bool done = false;
        while (j >= 3 && !done) {
            float2 a0 = sxyv[j], a1 = sxyv[j-1], a2 = sxyv[j-2], a3 = sxyv[j-3];
            float x0x, x1x, x2x, x3x;
            CAND(a0, j,   x0x); CAND(a1, j-1, x1x);
            CAND(a2, j-2, x2x); CAND(a3, j-3, x3x);
            done = (x3x > d5);             // dxx monotone; dd >= dxx -> safe
            j -= 4;
        }
        while (j >= 0 && !done) {
            float2 a0 = sxyv[j]; float xx;
            CAND(a0, j, xx);
            done = (xx > d5);
            j--;
        }
    } else {                               // rightward
        int j = p + 1; bool done = false;
        while (j <= Nv - 4 && !done) {
            float2 a0 = sxyv[j], a1 = sxyv[j+1], a2 = sxyv[j+2], a3 = sxyv[j+3];
            float x0x, x1x, x2x, x3x;
            CAND(a0, j,   x0x); CAND(a1, j+1, x1x);
            CAND(a2, j+2, x2x); CAND(a3, j+3, x3x);
            done = (x3x > d5);
            j += 4;
        }
        while (j < Nv && !done) {
            float2 a0 = sxyv[j]; float xx;
            CAND(a0, j, xx);
            done = (xx > d5);
            j++;
        }
        pdm[rloc*Kv+0]=d0; pdm[rloc*Kv+1]=d1; pdm[rloc*Kv+2]=d2;
        pdm[rloc*Kv+3]=d3; pdm[rloc*Kv+4]=d4; pdm[rloc*Kv+5]=d5;
        pim[rloc*Kv+0]=i0; pim[rloc*Kv+1]=i1; pim[rloc*Kv+2]=i2;
        pim[rloc*Kv+3]=i3; pim[rloc*Kv+4]=i4; pim[rloc*Kv+5]=i5;
    }
#undef CAND
#undef INS
    __syncthreads();

    if (dir == 0) {                        // merge: two-pointer, 6 steps
        float b0=pdm[rloc*Kv+0], b1=pdm[rloc*Kv+1], b2=pdm[rloc*Kv+2],
              b3=pdm[rloc*Kv+3], b4=pdm[rloc*Kv+4], b5=pdm[rloc*Kv+5];
        int   y0=pim[rloc*Kv+0], y1=pim[rloc*Kv+1], y2=pim[rloc*Kv+2],
              y3=pim[rloc*Kv+3], y4=pim[rloc*Kv+4], y5=pim[rloc*Kv+5];
#pragma unroll
        for (int s = 0; s < Kv; s++) {
            bool ta = (d0 <= b0);
            int sel = ta ? i0 : y0;
            snb[rloc * Kv + s] = s0s[sel];
            if (ta) { d0=d1; d1=d2; d2=d3; d3=d4; d4=d5; d5=FLT_MAX;
                      i0=i1; i1=i2; i2=i3; i3=i4; i4=i5; }
            else    { b0=b1; b1=b2; b2=b3; b3=b4; b4=b5; b5=FLT_MAX;
                      y0=y1; y1=y2; y2=y3; y3=y4; y4=y5; }
        }
        int orig = sid[p];
        srow[rloc] = make_float4(mx, my, deadline[(size_t)b * Nv + orig],
                                 __int_as_float(orig));
    }
    __syncthreads();

    // ---- phase 3: features; thread t = (d = t&127, row-half = t>>7) ----
    const int d  = t & (Dv - 1);
    const int rh = t >> 7;                 // 64 rows each
    const float4 w = sW3[d];
    float A[Kv], Bc[Kv];
#pragma unroll
    for (int k = 0; k < Kv; k++) { float2 ab = sAB[k * Dv + d]; A[k] = ab.x; Bc[k] = ab.y; }

    float acc = 0.f;
#pragma unroll 2
    for (int r = 0; r < 64; r++) {
        int rr = rh * 64 + r;
        float4 rd = srow[rr];              // broadcast LDS.128
        float v = w.w;
        v = fmaf(rd.x, w.x, v);
        v = fmaf(rd.y, w.y, v);
        v = fmaf(rd.z, w.z, v);
#pragma unroll
        for (int k = 0; k < Kv; k++) {
            float2 nb = snb[rr * Kv + k];  // broadcast LDS.64
            v = fmaf(nb.x, A[k], v);
            v = fmaf(nb.y, Bc[k], v);
        }
        v = fmaxf(v, 0.01f * v);           // leaky_relu(0.01)
        int orow = __float_as_int(rd.w);
        h_out[((size_t)b * 1025 + 1 + orow) * Dv + d] = v;
        acc += v;
    }
    g_partial[(((size_t)b * CHUNKS + chunk) * 2 + rh) * Dv + d] = acc;

    // ---- fused tail: last block computes depot row + means ----
    __threadfence();
    if (t == 0) sLast = (atomicAdd(&g_count, 1) == CHUNKS * Bv - 1) ? 1 : 0;
    __syncthreads();
    if (sLast) {
        if (t < Dv) {
            float w0 = Wdep[t * 2 + 0], w1 = Wdep[t * 2 + 1], bd = bdep[t];
            for (int bb = 0; bb < Bv; bb++) {
                float v = bd;
                v = fmaf(depot[bb * 2 + 0], w0, v);
                v = fmaf(depot[bb * 2 + 1], w1, v);
                v = fmaxf(v, 0.01f * v);
                h_out[(size_t)bb * 1025 * Dv + t] = v;   // h[bb, 0, d]
                float s = v;
#pragma unroll
                for (int c = 0; c < CHUNKS * 2; c++)
                    s += g_partial[((size_t)bb * CHUNKS * 2 + c) * Dv + t];
                h_out[(size_t)Bv * 1025 * Dv + bb * Dv + t] = s / 1025.0f;
            }
        }
        if (t == 0) g_count = 0;           // reset for next graph replay
    }
}

// ---------------------------------------------------------------------------
extern "C" void kernel_launch(void* const* d_in, const int* in_sizes, int n_in,
                              void* d_out, int out_size)
{
    const float* loc      = (const float*)d_in[0];
    const float* deadline = (const float*)d_in[1];
    const float* depot    = (const float*)d_in[2];
    const float* W3d      = (const float*)d_in[3];
    const float* b3d      = (const float*)d_in[4];
    const float* W2d      = (const float*)d_in[5];
    const float* b2d      = (const float*)d_in[6];
    const float* Wnb      = (const float*)d_in[7];
    const float* bnb      = (const float*)d_in[8];
    const float* Wdep     = (const float*)d_in[9];
    const float* bdep     = (const float*)d_in[10];
    float* out = (float*)d_out;

    setup_kernel<<<Bv + 48, 512>>>(loc, W2d, b2d, Wnb);
    dim3 grid(CHUNKS, Bv);
    main_kernel<<<grid, 256>>>(deadline, W3d, b3d, bnb,
                               depot, Wdep, bdep, out);
}

// round 5
// speedup vs baseline: 1.0523x; 1.0523x over previous
#include <cuda_runtime.h>
#include <float.h>

#define Bv 64
#define Nv 1024
#define Dv 128
#define Kv 6
#define CHUNKS 8          // 128 rows per main block, grid = 8 x 64 = 512
#define THR 128

__device__ float  g_ABC[Kv * Dv * 3];           // [k][d][{A,B,C}]
__device__ float  g_partial[Bv * CHUNKS * Dv];  // [b][chunk][d]
__device__ float4 g_sorted[Bv * Nv];            // (xb, yb, x0[orig], y0[orig])
__device__ int    g_sid[Bv * Nv];               // orig index, sorted order
__device__ int    g_count;                      // completion counter (self-resets)

// ---------------------------------------------------------------------------
// Setup: blocks 0..63 -> per-batch bitonic x-sort; 64..111 -> ABC weight fold
// ---------------------------------------------------------------------------
__global__ __launch_bounds__(512) void setup_kernel(
    const float* __restrict__ loc,
    const float* __restrict__ W2d, const float* __restrict__ b2d,
    const float* __restrict__ Wnb)
{
    __shared__ float kx[Nv];
    __shared__ float ky[Nv];
    __shared__ int   kid[Nv];
    const int t = threadIdx.x;

    if (blockIdx.x >= Bv) {
        int wid  = (blockIdx.x - Bv) * 16 + (t >> 5);   // 768 warps = 6k x 128d
        int k    = wid >> 7, d = wid & (Dv - 1);
        int lane = t & 31;
        const float4* w4 = (const float4*)(Wnb + (size_t)d * (Kv * Dv) + k * Dv);
        float4 v  = w4[lane];
        const float4* w2 = (const float4*)W2d;
        float4 p0 = w2[lane * 2], p1 = w2[lane * 2 + 1];
        float4 bb = ((const float4*)b2d)[lane];
        float A = fmaf(v.x, p0.x, fmaf(v.y, p0.z, fmaf(v.z, p1.x, v.w * p1.z)));
        float B = fmaf(v.x, p0.y, fmaf(v.y, p0.w, fmaf(v.z, p1.y, v.w * p1.w)));
        float C = fmaf(v.x, bb.x, fmaf(v.y, bb.y, fmaf(v.z, bb.z, v.w * bb.w)));
#pragma unroll
        for (int s = 16; s > 0; s >>= 1) {
            A += __shfl_xor_sync(0xffffffffu, A, s);
            B += __shfl_xor_sync(0xffffffffu, B, s);
            C += __shfl_xor_sync(0xffffffffu, C, s);
        }
        if (lane == 0) {
            int base = (k * Dv + d) * 3;
            g_ABC[base + 0] = A; g_ABC[base + 1] = B; g_ABC[base + 2] = C;
        }
        return;
    }

    const int b = blockIdx.x;
    const float2* lb = (const float2*)(loc + (size_t)b * Nv * 2);
    for (int i = t; i < Nv; i += 512) {
        float2 p = lb[i];
        kx[i] = p.x; ky[i] = p.y; kid[i] = i;
    }
    __syncthreads();
    for (int k = 2; k <= Nv; k <<= 1) {
        for (int j = k >> 1; j > 0; j >>= 1) {
            for (int i = t; i < Nv; i += 512) {
                int ixj = i ^ j;
                if (ixj > i) {
                    bool up = ((i & k) == 0);
                    float xa = kx[i], xb = kx[ixj];
                    if (up ? (xa > xb) : (xa < xb)) {
                        kx[i] = xb; kx[ixj] = xa;
                        float ya = ky[i]; ky[i] = ky[ixj]; ky[ixj] = ya;
                        int ia = kid[i]; kid[i] = kid[ixj]; kid[ixj] = ia;
                    }
                }
            }
            __syncthreads();
        }
    }
    const float2* l0 = (const float2*)loc;
    for (int i = t; i < Nv; i += 512) {
        int gid = kid[i];
        float2 p0 = l0[gid];
        g_sorted[(size_t)b * Nv + i] = make_float4(kx[i], ky[i], p0.x, p0.y);
        g_sid[(size_t)b * Nv + i]    = gid;
    }
}

// ---------------------------------------------------------------------------
// Main: 128 threads = 128 rows. Warp-uniform union-window scan:
//   lanes own 32 consecutive sorted rows; all lanes process the SAME candidate
//   stream (32 internal, then outward L/R groups of 4). INS is a no-op when
//   dd > d5, so no divergent branches; continuation = one warp-vote per group.
// ---------------------------------------------------------------------------
__global__ __launch_bounds__(THR) void main_kernel(
    const float* __restrict__ deadline,
    const float* __restrict__ W3d, const float* __restrict__ b3d,
    const float* __restrict__ bnb,
    const float* __restrict__ depot, const float* __restrict__ Wdep,
    const float* __restrict__ bdep, float* __restrict__ h_out)
{
    __shared__ float2 sxyv[Nv];        // sorted batch-b coords       8 KB
    __shared__ float2 s0s[Nv];         // batch-0 coords, sorted ord  8 KB
    __shared__ float4 srow[THR];       // (x, y, deadline, origbits)  2 KB
    __shared__ float2 snb[THR * Kv];   // neighbor batch-0 coords     6 KB
    __shared__ float4 sW3[Dv];         // (w0,w1,w2, base)            2 KB
    __shared__ float2 sAB[Kv * Dv];    // (A_k[d], B_k[d])            6 KB
    __shared__ int    sLast;

    const int b = blockIdx.y, chunk = blockIdx.x, t = threadIdx.x;

    {
        const float4* gs = g_sorted + (size_t)b * Nv;
#pragma unroll
        for (int i = 0; i < Nv / THR; i++) {
            float4 q = gs[i * THR + t];
            sxyv[i * THR + t] = make_float2(q.x, q.y);
            s0s[i * THR + t]  = make_float2(q.z, q.w);
        }
    }
    {
        float sumC = 0.f;
#pragma unroll
        for (int k = 0; k < Kv; k++) {
            int base = (k * Dv + t) * 3;
            sAB[k * Dv + t] = make_float2(g_ABC[base], g_ABC[base + 1]);
            sumC += g_ABC[base + 2];
        }
        sW3[t] = make_float4(W3d[t * 3 + 0], W3d[t * 3 + 1], W3d[t * 3 + 2],
                             b3d[t] + bnb[t] + sumC);
    }
    __syncthreads();

    // ---- phase 2: warp-uniform scan ----
    const int w    = t >> 5;                  // warp 0..3
    const int base = chunk * THR + w * 32;    // warp's first sorted row
    const int p    = base + (t & 31);         // this lane's row
    const float2 m = sxyv[p];
    const float mx = m.x, my = m.y;

    float d0 = FLT_MAX, d1 = FLT_MAX, d2 = FLT_MAX,
          d3 = FLT_MAX, d4 = FLT_MAX, d5 = FLT_MAX;
    int   i0 = 0, i1 = 0, i2 = 0, i3 = 0, i4 = 0, i5 = 0;

#define INS(dd, cj)  do {                                                    \
        bool c0 = dd < d0, c1 = dd < d1, c2 = dd < d2,                       \
             c3 = dd < d3, c4 = dd < d4, c5 = dd < d5;                       \
        float m0 = fmaxf(d0, dd), m1 = fmaxf(d1, dd), m2 = fmaxf(d2, dd),    \
              m3 = fmaxf(d3, dd), m4 = fmaxf(d4, dd);                        \
        int   w0 = c0 ? i0 : cj, w1 = c1 ? i1 : cj, w2 = c2 ? i2 : cj,       \
              w3 = c3 ? i3 : cj, w4 = c4 ? i4 : cj;                          \
        d5 = c5 ? m4 : d5;  i5 = c5 ? w4 : i5;                               \
        d4 = c4 ? m3 : d4;  i4 = c4 ? w3 : i4;                               \
        d3 = c3 ? m2 : d3;  i3 = c3 ? w2 : i3;                               \
        d2 = c2 ? m1 : d2;  i2 = c2 ? w1 : i2;                               \
        d1 = c1 ? m0 : d1;  i1 = c1 ? w0 : i1;                               \
        d0 = c0 ? dd : d0;  i0 = c0 ? cj : i0;                               \
    } while (0)

#define CAND(cj, DXX) {                                                     \
        float2 cv = sxyv[cj];                                               \
        float dx  = __fadd_rn(cv.x, -mx);                                   \
        float dy  = __fadd_rn(cv.y, -my);                                   \
        DXX = __fmul_rn(dx, dx);                                            \
        float dd  = __fadd_rn(DXX, __fmul_rn(dy, dy));                      \
        INS(dd, cj);                                                        \
    }

    {   // internal 32 candidates (includes self: dd = 0 self-inserts)
        float dxx;
#pragma unroll 4
        for (int q = 0; q < 32; q++) CAND(base + q, dxx);
    }
    {   // leftward, groups of 4, warp-vote prune on farthest candidate
        int j = base - 1; bool go = (j >= 0);
        while (go && j >= 3) {
            float x0x, x1x, x2x, x3x;
            CAND(j, x0x); CAND(j-1, x1x); CAND(j-2, x2x); CAND(j-3, x3x);
            go = __any_sync(0xffffffffu, x3x <= d5);  // dxx monotone; dd >= dxx
            j -= 4;
        }
        while (go && j >= 0) {
            float xx; CAND(j, xx);
            go = __any_sync(0xffffffffu, xx <= d5);
            j--;
        }
    }
    {   // rightward
        int j = base + 32; bool go = (j < Nv);
        while (go && j <= Nv - 4) {
            float x0x, x1x, x2x, x3x;
            CAND(j, x0x); CAND(j+1, x1x); CAND(j+2, x2x); CAND(j+3, x3x);
            go = __any_sync(0xffffffffu, x3x <= d5);
            j += 4;
        }
        while (go && j < Nv) {
            float xx; CAND(j, xx);
            go = __any_sync(0xffffffffu, xx <= d5);
            j++;
        }
    }
#undef CAND
#undef INS

    const int rloc = t;                    // one row per thread
    snb[rloc*Kv+0] = s0s[i0]; snb[rloc*Kv+1] = s0s[i1]; snb[rloc*Kv+2] = s0s[i2];
    snb[rloc*Kv+3] = s0s[i3]; snb[rloc*Kv+4] = s0s[i4]; snb[rloc*Kv+5] = s0s[i5];
    {
        int orig = g_sid[(size_t)b * Nv + p];
        srow[rloc] = make_float4(mx, my, deadline[(size_t)b * Nv + orig],
                                 __int_as_float(orig));
    }
    __syncthreads();

    // ---- phase 3: features; thread t = dim d, loop over 128 rows ----
    const int d    = t;
    const float4 wv = sW3[d];
    float A[Kv], Bc[Kv];
#pragma unroll
    for (int k = 0; k < Kv; k++) { float2 ab = sAB[k * Dv + d]; A[k] = ab.x; Bc[k] = ab.y; }

    float acc = 0.f;
#pragma unroll 2
    for (int r = 0; r < THR; r++) {
        float4 rd = srow[r];               // broadcast LDS.128
        float v = wv.w;
        v = fmaf(rd.x, wv.x, v);
        v = fmaf(rd.y, wv.y, v);
        v = fmaf(rd.z, wv.z, v);
#pragma unroll
        for (int k = 0; k < Kv; k++) {
            float2 nb = snb[r * Kv + k];   // broadcast LDS.64
            v = fmaf(nb.x, A[k], v);
            v = fmaf(nb.y, Bc[k], v);
        }
        v = fmaxf(v, 0.01f * v);           // leaky_relu(0.01)
        int orow = __float_as_int(rd.w);
        h_out[((size_t)b * 1025 + 1 + orow) * Dv + d] = v;
        acc += v;
    }
    g_partial[((size_t)b * CHUNKS + chunk) * Dv + d] = acc;

    // ---- fused tail: last finishing block computes depot row + means ----
    __threadfence();
    if (t == 0) sLast = (atomicAdd(&g_count, 1) == CHUNKS * Bv - 1) ? 1 : 0;
    __syncthreads();
    if (sLast) {
        float w0 = Wdep[t * 2 + 0], w1 = Wdep[t * 2 + 1], bd = bdep[t];
        for (int bb = 0; bb < Bv; bb++) {
            float v = bd;
            v = fmaf(depot[bb * 2 + 0], w0, v);
            v = fmaf(depot[bb * 2 + 1], w1, v);
            v = fmaxf(v, 0.01f * v);
            h_out[(size_t)bb * 1025 * Dv + t] = v;       // h[bb, 0, d]
            float s = v;
#pragma unroll
            for (int c = 0; c < CHUNKS; c++)
                s += g_partial[((size_t)bb * CHUNKS + c) * Dv + t];
            h_out[(size_t)Bv * 1025 * Dv + bb * Dv + t] = s / 1025.0f;
        }
        if (t == 0) g_count = 0;           // reset for next graph replay
    }
}

// ---------------------------------------------------------------------------
extern "C" void kernel_launch(void* const* d_in, const int* in_sizes, int n_in,
                              void* d_out, int out_size)
{
    const float* loc      = (const float*)d_in[0];
    const float* deadline = (const float*)d_in[1];
    const float* depot    = (const float*)d_in[2];
    const float* W3d      = (const float*)d_in[3];
    const float* b3d      = (const float*)d_in[4];
    const float* W2d      = (const float*)d_in[5];
    const float* b2d      = (const float*)d_in[6];
    const float* Wnb      = (const float*)d_in[7];
    const float* bnb      = (const float*)d_in[8];
    const float* Wdep     = (const float*)d_in[9];
    const float* bdep     = (const float*)d_in[10];
    float* out = (float*)d_out;

    setup_kernel<<<Bv + 48, 512>>>(loc, W2d, b2d, Wnb);
    dim3 grid(CHUNKS, Bv);
    main_kernel<<<grid, THR>>>(deadline, W3d, b3d, bnb,
                               depot, Wdep, bdep, out);
}